// round 15
// baseline (speedup 1.0000x reference)
#include <cuda_runtime.h>

// Problem constants
#define NMESH 31
#define BB    2
#define JJ    768
#define CC    4
#define NBG   6
#define TWOPI_L 0.31415926535897931f   // 2*pi/20
#define VBOX  8000.0f

// Padded half-space mode box: a in [0,16), bb,cc in [0,31). idx = a*961+bb*31+cc
#define NA    16
#define NROWS (NA * 31)                // 496
#define PLANE (NROWS * 31)             // 15376
#define NCHK  6                        // nufft1 particle chunks (2 O + 4 H), 128 each
#define NSPLIT 16                      // nufft2: one a-value per block
#define NP2   32                       // particles per nufft2 block

typedef unsigned long long ull;

// ---- packed f32x2 helpers (Blackwell sm_100+) ----
#define PACKF(out, lo, hi) do { unsigned _plo = __float_as_uint(lo), _phi = __float_as_uint(hi); \
    asm("mov.b64 %0, {%1, %2};" : "=l"(out) : "r"(_plo), "r"(_phi)); } while(0)
#define UNPACKF(lo, hi, in) do { unsigned _ulo, _uhi; \
    asm("mov.b64 {%0, %1}, %2;" : "=r"(_ulo), "=r"(_uhi) : "l"(in)); \
    (lo) = __uint_as_float(_ulo); (hi) = __uint_as_float(_uhi); } while(0)
#define FMA2(d,a,b,c) asm("fma.rn.f32x2 %0, %1, %2, %3;" : "=l"(d) : "l"(a), "l"(b), "l"(c))
#define MUL2(d,a,b)   asm("mul.rn.f32x2 %0, %1, %2;"     : "=l"(d) : "l"(a), "l"(b))
#define ADD2(d,a,b)   asm("add.rn.f32x2 %0, %1, %2;"     : "=l"(d) : "l"(a), "l"(b))

// Scratch (allocation-free rule -> __device__ globals)
__device__ float2 g_Ez [BB][JJ][NMESH];          // e^{-i m z}
__device__ float2 g_Exy[BB][NROWS][JJ];          // Ex[a]*Ey[bb] per particle
__device__ float4 g_r  [BB][NCHK][PLANE][2];     // nufft1 partials per chunk
__device__ float4 g_f  [BB][2][PLANE][2];        // mixed + weight-folded grid
__device__ float  g_gexp[4][NBG];                // exp(2*shift) per species pair
__device__ float  g_part[NSPLIT][BB][JJ][4];     // nufft2 partials (e, fx, fy, fz)

__device__ __forceinline__ float2 cmul(float2 a, float2 b) {
    return make_float2(a.x*b.x - a.y*b.y, a.x*b.y + a.y*b.x);
}

// ---------------------------------------------------------------------------
// Kernel 1: phase tables, parallel over (a, particle) + tiny exp(2s) table.
// ---------------------------------------------------------------------------
__global__ __launch_bounds__(256) void phase_kernel(
    const float* __restrict__ pos,
    const float* __restrict__ sOO, const float* __restrict__ sOH,
    const float* __restrict__ sHO, const float* __restrict__ sHH)
{
    int t = blockIdx.x * blockDim.x + threadIdx.x;
    int total_xy = NA * BB * JJ;
    if (t < total_xy) {
        int a = t / (BB * JJ);
        int bj = t - a * (BB * JJ);
        int b = bj / JJ, j = bj % JJ;
        const float* p = pos + (size_t)bj * 3;
        float angx = TWOPI_L * (p[0] - 10.0f);
        float angy = TWOPI_L * (p[1] - 10.0f);
        float sx, cx, sy, cy;
        sincosf(angx, &sx, &cx);
        sincosf(angy, &sy, &cy);
        float2 ex1 = make_float2(cx, -sx);
        float2 ey1 = make_float2(cy, -sy);
        float2 ex2 = cmul(ex1, ex1), ex4 = cmul(ex2, ex2), ex8 = cmul(ex4, ex4);
        float2 exa = make_float2(1.0f, 0.0f);
        if (a & 1) exa = cmul(exa, ex1);
        if (a & 2) exa = cmul(exa, ex2);
        if (a & 4) exa = cmul(exa, ex4);
        if (a & 8) exa = cmul(exa, ex8);
        float2 ey2 = cmul(ey1, ey1), ey4 = cmul(ey2, ey2), ey8 = cmul(ey4, ey4);
        float2 ey15 = cmul(cmul(ey8, ey4), cmul(ey2, ey1));
        float2 cur = cmul(exa, make_float2(ey15.x, -ey15.y));
        #pragma unroll
        for (int bb = 0; bb < 31; bb++) {
            g_Exy[b][a * 31 + bb][j] = cur;
            cur = cmul(cur, ey1);
        }
    } else if (t < total_xy + BB * JJ) {
        int bj = t - total_xy;
        int b = bj / JJ, j = bj % JJ;
        const float* p = pos + (size_t)bj * 3;
        float ang = TWOPI_L * (p[2] - 10.0f);
        float s, c; sincosf(ang, &s, &c);
        float2 e1 = make_float2(c, -s);
        float2 e2 = cmul(e1, e1), e4 = cmul(e2, e2), e8 = cmul(e4, e4);
        float2 e15 = cmul(cmul(e8, e4), cmul(e2, e1));
        float2 cur = make_float2(e15.x, -e15.y);
        #pragma unroll
        for (int cc = 0; cc < 31; cc++) {
            g_Ez[b][j][cc] = cur;
            cur = cmul(cur, e1);
        }
    } else if (t < total_xy + BB * JJ + 4 * NBG) {
        int idx = t - total_xy - BB * JJ;
        int k = idx / NBG, n = idx % NBG;
        const float* sp = (k == 0) ? sOO : (k == 1) ? sOH : (k == 2) ? sHO : sHH;
        g_gexp[k][n] = expf(2.0f * sp[n]);
    }
}

// ---------------------------------------------------------------------------
// Kernel 2: nufft1 scalar, warp = ONE row, 256 threads (8 rows/block).
// lane = cc; 128-particle chunk staged in 32-particle tiles.
// grid = 2b * 6 chunks * 62 rowblocks = 744; 5952 warps total (~63% occ).
// ---------------------------------------------------------------------------
__global__ __launch_bounds__(256) void nufft1_kernel(const float* __restrict__ charge) {
    int blk = blockIdx.x;
    int rowblk = blk % 62;  blk /= 62;
    int chunk = blk % NCHK; int b = blk / NCHK;
    int w = threadIdx.x >> 5, l = threadIdx.x & 31;
    int rowbase = rowblk * 8;
    int row = rowbase + w;
    int jbase = chunk * 128;

    __shared__ float2 shEz[32][32];   // col 31 zeroed (lane-31 mask)
    __shared__ float4 shq[32];
    __shared__ float2 shxy[8][32];    // [block-row][particle]

    float aR0 = 0.f, aI0 = 0.f, aR1 = 0.f, aI1 = 0.f;
    float aR2 = 0.f, aI2 = 0.f, aR3 = 0.f, aI3 = 0.f;

    for (int j0 = 0; j0 < 128; j0 += 32) {
        __syncthreads();
        for (int idx = threadIdx.x; idx < 32 * 32; idx += 256) {
            int jj = idx >> 5, cc = idx & 31;
            shEz[jj][cc] = (cc < 31) ? g_Ez[b][jbase + j0 + jj][cc]
                                     : make_float2(0.f, 0.f);
        }
        if (threadIdx.x < 32) {
            const float4* q = (const float4*)(charge + (size_t)(b * JJ + jbase + j0 + threadIdx.x) * 4);
            shq[threadIdx.x] = *q;
        }
        if (threadIdx.x < 8 * 32) {
            int rr = threadIdx.x >> 5, jj = threadIdx.x & 31;
            shxy[rr][jj] = g_Exy[b][rowbase + rr][jbase + j0 + jj];
        }
        __syncthreads();
        #pragma unroll 4
        for (int jj = 0; jj < 32; jj++) {
            float2 ez = shEz[jj][l];
            float4 q  = shq[jj];
            float2 t0 = shxy[w][jj];
            float pr = t0.x*ez.x - t0.y*ez.y;
            float pi = t0.x*ez.y + t0.y*ez.x;
            aR0 += q.x*pr; aI0 += q.x*pi;
            aR1 += q.y*pr; aI1 += q.y*pi;
            aR2 += q.z*pr; aI2 += q.z*pi;
            aR3 += q.w*pr; aI3 += q.w*pi;
        }
    }
    if (l < 31) {
        int i0 = row * 31 + l;
        g_r[b][chunk][i0][0] = make_float4(aR0, aI0, aR1, aI1);
        g_r[b][chunk][i0][1] = make_float4(aR2, aI2, aR3, aI3);
    }
}

// ---------------------------------------------------------------------------
// Kernel 3: SOG multipliers (gaussian widths from table) + mix + merge + fold.
// ---------------------------------------------------------------------------
__global__ __launch_bounds__(256) void combine_kernel(
    const float* __restrict__ aOO, const float* __restrict__ aOH,
    const float* __restrict__ aHO, const float* __restrict__ aHH)
{
    int idx = blockIdx.x * blockDim.x + threadIdx.x;
    if (idx >= PLANE) return;
    int cc = idx % 31; int t = idx / 31; int bbv = t % 31; int a = t / 31;
    float kx = TWOPI_L * a, ky = TWOPI_L * (bbv - 15), kz = TWOPI_L * (cc - 15);
    float squ = kx*kx + ky*ky + kz*kz;

    bool valid = (a > 0) || (bbv > 15) || (bbv == 15 && cc >= 15);
    bool k0    = (a == 0 && bbv == 15 && cc == 15);

    float mOO = 0.f, mOH = 0.f, mHO = 0.f, mHH = 0.f;
    #pragma unroll
    for (int n = 0; n < NBG; n++) {
        mOO += aOO[n] * expf(-squ * g_gexp[0][n]);
        mOH += aOH[n] * expf(-squ * g_gexp[1][n]);
        mHO += aHO[n] * expf(-squ * g_gexp[2][n]);
        mHH += aHH[n] * expf(-squ * g_gexp[3][n]);
    }
    if (k0) { mOH = 0.f; mHO = 0.f; mHH = 0.f; }
    float wgt = valid ? (k0 ? 1.0f : 2.0f) : 0.0f;
    mOO *= wgt; mOH *= wgt; mHO *= wgt; mHH *= wgt;

    #pragma unroll
    for (int b = 0; b < BB; b++) {
        #pragma unroll
        for (int h = 0; h < 2; h++) {
            float4 c0 = g_r[b][0][idx][h];
            float4 c1 = g_r[b][1][idx][h];
            float4 c2 = g_r[b][2][idx][h];
            float4 c3 = g_r[b][3][idx][h];
            float4 c4 = g_r[b][4][idx][h];
            float4 c5 = g_r[b][5][idx][h];
            float4 rO = make_float4(c0.x + c1.x, c0.y + c1.y, c0.z + c1.z, c0.w + c1.w);
            float4 rH = make_float4(c2.x + c3.x + c4.x + c5.x, c2.y + c3.y + c4.y + c5.y,
                                    c2.z + c3.z + c4.z + c5.z, c2.w + c3.w + c4.w + c5.w);
            g_f[b][0][idx][h] = make_float4(mOO*rO.x + mOH*rH.x, mOO*rO.y + mOH*rH.y,
                                            mOO*rO.z + mOH*rH.z, mOO*rO.w + mOH*rH.w);
            g_f[b][1][idx][h] = make_float4(mHO*rO.x + mHH*rH.x, mHO*rO.y + mHH*rH.y,
                                            mHO*rO.z + mHH*rH.z, mHO*rO.w + mHH*rH.w);
        }
    }
}

// ---------------------------------------------------------------------------
// Kernel 4: nufft2 (R12 measured-best: full staging, single sync).
// 8 warps x 4 particles; one a-value per block. grid = 48*16 = 768.
// ---------------------------------------------------------------------------
__global__ __launch_bounds__(256) void nufft2_kernel(const float* __restrict__ charge) {
    int blk = blockIdx.x;
    int split = blk & 15; int g = blk >> 4;
    int b = g / 24; int gg = g % 24;
    int s = (gg >= 8) ? 1 : 0;
    int pbase = (gg < 8) ? gg * NP2 : 256 + (gg - 8) * NP2;
    int w = threadIdx.x >> 5, l = threadIdx.x & 31;
    int lc = (l < 31) ? l : 30;
    int pb = w * 4;

    __shared__ float4 tileA[961];                  // f channels 0,1 (full a-plane)
    __shared__ float4 tileB[961];                  // f channels 2,3
    __shared__ ull shATx [31][16];                 // packed (Exy.x p0, p1)
    __shared__ ull shATyn[31][16];                 // packed (-Exy.y, -Exy.y)

    // ---- stage everything once ----
    {
        const float4* src = &g_f[b][s][split * 961][0];
        for (int t = threadIdx.x; t < 961; t += 256) {
            tileA[t] = src[2 * t];
            tileB[t] = src[2 * t + 1];
        }
        for (int t = threadIdx.x; t < 31 * 16; t += 256) {
            int rr = t >> 4; int pr = t & 15;
            float2 A0 = g_Exy[b][split * 31 + rr][pbase + 2 * pr];
            float2 A1 = g_Exy[b][split * 31 + rr][pbase + 2 * pr + 1];
            ull vx, vy;
            float n0 = -A0.y, n1 = -A1.y;
            PACKF(vx, A0.x, A1.x);
            PACKF(vy, n0, n1);
            shATx[rr][pr] = vx; shATyn[rr][pr] = vy;
        }
    }

    // per-pair packed constants
    ull ezx[2], ezy[2], ezyn[2];
    ull qx[2], qy[2], qz[2], qw[2];
    #pragma unroll
    for (int pr = 0; pr < 2; pr++) {
        int p0 = pbase + pb + 2 * pr, p1 = p0 + 1;
        float2 ea = (l < 31) ? g_Ez[b][p0][lc] : make_float2(0.f, 0.f);
        float2 eb = (l < 31) ? g_Ez[b][p1][lc] : make_float2(0.f, 0.f);
        PACKF(ezx[pr], ea.x, eb.x);
        PACKF(ezy[pr], ea.y, eb.y);
        float na = -ea.y, nb = -eb.y;
        PACKF(ezyn[pr], na, nb);
        float4 qa = *(const float4*)(charge + (size_t)(b * JJ + p0) * 4);
        float4 qb = *(const float4*)(charge + (size_t)(b * JJ + p1) * 4);
        PACKF(qx[pr], qa.x, qb.x); PACKF(qy[pr], qa.y, qb.y);
        PACKF(qz[pr], qa.z, qb.z); PACKF(qw[pr], qa.w, qb.w);
    }
    ull accE1[2] = {0ull, 0ull}, accE2[2] = {0ull, 0ull};
    ull accS[2] = {0ull, 0ull}, accY[2] = {0ull, 0ull};

    __syncthreads();

    for (int row = 0; row < 31; row++) {
        float4 fa = tileA[row * 31 + lc];
        float4 fb = tileB[row * 31 + lc];
        ull f0r, f0i, f1r, f1i, f2r, f2i, f3r, f3i, kys;
        PACKF(f0r, fa.x, fa.x); PACKF(f0i, fa.y, fa.y);
        PACKF(f1r, fa.z, fa.z); PACKF(f1i, fa.w, fa.w);
        PACKF(f2r, fb.x, fb.x); PACKF(f2i, fb.y, fb.y);
        PACKF(f3r, fb.z, fb.z); PACKF(f3i, fb.w, fb.w);
        float ky = TWOPI_L * (row - 15);
        PACKF(kys, ky, ky);
        #pragma unroll
        for (int pr = 0; pr < 2; pr++) {
            ull Ax  = shATx [row][2 * w + pr];
            ull Ayn = shATyn[row][2 * w + pr];
            ull tt, ur, uiN;
            MUL2(tt, Ayn, ezy[pr]); FMA2(ur,  Ax, ezx[pr],  tt);   //  Re u
            MUL2(tt, Ayn, ezx[pr]); FMA2(uiN, Ax, ezyn[pr], tt);   // -Im u
            ull fqr, fqi;
            MUL2(fqr, qw[pr], f3r); FMA2(fqr, qz[pr], f2r, fqr);
            FMA2(fqr, qy[pr], f1r, fqr); FMA2(fqr, qx[pr], f0r, fqr);
            MUL2(fqi, qw[pr], f3i); FMA2(fqi, qz[pr], f2i, fqi);
            FMA2(fqi, qy[pr], f1i, fqi); FMA2(fqi, qx[pr], f0i, fqi);
            FMA2(accE1[pr], fqr, ur,  accE1[pr]);                  // Σ fqr*ur
            FMA2(accE2[pr], fqi, uiN, accE2[pr]);                  // Σ fqi*(-ui)
            ull wi;
            MUL2(wi, fqr, uiN); FMA2(wi, fqi, ur, wi);             // Im(fq conj u)
            ADD2(accS[pr], accS[pr], wi);
            FMA2(accY[pr], kys, wi, accY[pr]);
        }
    }

    float kxv = TWOPI_L * split;
    float kzv = TWOPI_L * (l - 15);
    #pragma unroll
    for (int pr = 0; pr < 2; pr++) {
        float e1L, e1H, e2L, e2H, sL, sH, yL, yH;
        UNPACKF(e1L, e1H, accE1[pr]);
        UNPACKF(e2L, e2H, accE2[pr]);
        UNPACKF(sL, sH, accS[pr]);
        UNPACKF(yL, yH, accY[pr]);
        #pragma unroll
        for (int half = 0; half < 2; half++) {
            float e = (half ? e1H : e1L) - (half ? e2H : e2L);     // Re(fq conj u)
            float S = half ? sH : sL;
            float Y = half ? yH : yL;
            float Z = S * kzv;
            #pragma unroll
            for (int off = 16; off > 0; off >>= 1) {
                e += __shfl_xor_sync(0xffffffff, e, off);
                S += __shfl_xor_sync(0xffffffff, S, off);
                Y += __shfl_xor_sync(0xffffffff, Y, off);
                Z += __shfl_xor_sync(0xffffffff, Z, off);
            }
            if (l == 0) {
                int j = pbase + pb + 2 * pr + half;
                g_part[split][b][j][0] = e;
                g_part[split][b][j][1] = kxv * S;
                g_part[split][b][j][2] = Y;
                g_part[split][b][j][3] = Z;
            }
        }
    }
}

// ---------------------------------------------------------------------------
// Kernel 5: deterministic fixed-order reduction of split partials.
// ---------------------------------------------------------------------------
__global__ __launch_bounds__(256) void finalize_kernel(float* __restrict__ out) {
    int t = blockIdx.x * blockDim.x + threadIdx.x;
    if (t >= BB * JJ) return;
    int b = t / JJ, j = t % JJ;
    float e = 0.f, fx = 0.f, fy = 0.f, fz = 0.f;
    #pragma unroll
    for (int sp = 0; sp < NSPLIT; sp++) {
        e  += g_part[sp][b][j][0];
        fx += g_part[sp][b][j][1];
        fy += g_part[sp][b][j][2];
        fz += g_part[sp][b][j][3];
    }
    out[t] = e * (1.0f / (2.0f * VBOX));
    float* F = out + BB * JJ;
    F[(size_t)t * 3 + 0] = fx * (1.0f / VBOX);
    F[(size_t)t * 3 + 1] = fy * (1.0f / VBOX);
    F[(size_t)t * 3 + 2] = fz * (1.0f / VBOX);
}

// ---------------------------------------------------------------------------
extern "C" void kernel_launch(void* const* d_in, const int* in_sizes, int n_in,
                              void* d_out, int out_size) {
    const float* pos    = (const float*)d_in[0];
    const float* charge = (const float*)d_in[1];

    int phase_threads = (NA + 1) * BB * JJ + 4 * NBG;
    phase_kernel<<<(phase_threads + 255) / 256, 256>>>(
        pos, (const float*)d_in[2], (const float*)d_in[4],
        (const float*)d_in[6], (const float*)d_in[8]);
    nufft1_kernel<<<BB * NCHK * 62, 256>>>(charge);
    combine_kernel<<<(PLANE + 255) / 256, 256>>>(
        (const float*)d_in[3], (const float*)d_in[5],
        (const float*)d_in[7], (const float*)d_in[9]);
    nufft2_kernel<<<48 * NSPLIT, 256>>>(charge);
    finalize_kernel<<<(BB * JJ + 255) / 256, 256>>>((float*)d_out);
}

// round 16
// speedup vs baseline: 1.1040x; 1.1040x over previous
#include <cuda_runtime.h>

// Problem constants
#define NMESH 31
#define BB    2
#define JJ    768
#define CC    4
#define NBG   6
#define TWOPI_L 0.31415926535897931f   // 2*pi/20
#define VBOX  8000.0f

// Padded half-space mode box: a in [0,16), bb,cc in [0,31). idx = a*961+bb*31+cc
#define NA    16
#define NROWS (NA * 31)                // 496
#define PLANE (NROWS * 31)             // 15376
#define NCHK  6                        // nufft1 particle chunks (2 O + 4 H), 128 each
#define NSPLIT 16                      // nufft2: one a-value per block
#define NP2   32                       // particles per nufft2 block
#define NGRP  48                       // nufft2 particle groups (blk >> 4)

typedef unsigned long long ull;

// ---- packed f32x2 helpers (Blackwell sm_100+) ----
#define PACKF(out, lo, hi) do { unsigned _plo = __float_as_uint(lo), _phi = __float_as_uint(hi); \
    asm("mov.b64 %0, {%1, %2};" : "=l"(out) : "r"(_plo), "r"(_phi)); } while(0)
#define UNPACKF(lo, hi, in) do { unsigned _ulo, _uhi; \
    asm("mov.b64 {%0, %1}, %2;" : "=r"(_ulo), "=r"(_uhi) : "l"(in)); \
    (lo) = __uint_as_float(_ulo); (hi) = __uint_as_float(_uhi); } while(0)
#define FMA2(d,a,b,c) asm("fma.rn.f32x2 %0, %1, %2, %3;" : "=l"(d) : "l"(a), "l"(b), "l"(c))
#define MUL2(d,a,b)   asm("mul.rn.f32x2 %0, %1, %2;"     : "=l"(d) : "l"(a), "l"(b))
#define ADD2(d,a,b)   asm("add.rn.f32x2 %0, %1, %2;"     : "=l"(d) : "l"(a), "l"(b))

// Scratch (allocation-free rule -> __device__ globals)
__device__ float2 g_Ez [BB][JJ][NMESH];          // e^{-i m z}
__device__ float2 g_Exy[BB][NROWS][JJ];          // Ex[a]*Ey[bb] per particle
__device__ float4 g_r  [BB][NCHK][PLANE][2];     // nufft1 partials per chunk
__device__ float4 g_f  [BB][2][PLANE][2];        // mixed + weight-folded grid
__device__ float  g_gexp[4][NBG];                // exp(2*shift) per species pair
__device__ float  g_part[NSPLIT][BB][JJ][4];     // nufft2 partials (e, fx, fy, fz)
__device__ int    g_done[NGRP];                  // completion counters (reset each launch)

__device__ __forceinline__ float2 cmul(float2 a, float2 b) {
    return make_float2(a.x*b.x - a.y*b.y, a.x*b.y + a.y*b.x);
}

// ---------------------------------------------------------------------------
// Kernel 1: phase tables, parallel over (a, particle) + exp(2s) table
//           + completion-counter reset.
// ---------------------------------------------------------------------------
__global__ __launch_bounds__(256) void phase_kernel(
    const float* __restrict__ pos,
    const float* __restrict__ sOO, const float* __restrict__ sOH,
    const float* __restrict__ sHO, const float* __restrict__ sHH)
{
    int t = blockIdx.x * blockDim.x + threadIdx.x;
    int total_xy = NA * BB * JJ;
    if (t < total_xy) {
        int a = t / (BB * JJ);
        int bj = t - a * (BB * JJ);
        int b = bj / JJ, j = bj % JJ;
        const float* p = pos + (size_t)bj * 3;
        float angx = TWOPI_L * (p[0] - 10.0f);
        float angy = TWOPI_L * (p[1] - 10.0f);
        float sx, cx, sy, cy;
        sincosf(angx, &sx, &cx);
        sincosf(angy, &sy, &cy);
        float2 ex1 = make_float2(cx, -sx);
        float2 ey1 = make_float2(cy, -sy);
        float2 ex2 = cmul(ex1, ex1), ex4 = cmul(ex2, ex2), ex8 = cmul(ex4, ex4);
        float2 exa = make_float2(1.0f, 0.0f);
        if (a & 1) exa = cmul(exa, ex1);
        if (a & 2) exa = cmul(exa, ex2);
        if (a & 4) exa = cmul(exa, ex4);
        if (a & 8) exa = cmul(exa, ex8);
        float2 ey2 = cmul(ey1, ey1), ey4 = cmul(ey2, ey2), ey8 = cmul(ey4, ey4);
        float2 ey15 = cmul(cmul(ey8, ey4), cmul(ey2, ey1));
        float2 cur = cmul(exa, make_float2(ey15.x, -ey15.y));
        #pragma unroll
        for (int bb = 0; bb < 31; bb++) {
            g_Exy[b][a * 31 + bb][j] = cur;
            cur = cmul(cur, ey1);
        }
    } else if (t < total_xy + BB * JJ) {
        int bj = t - total_xy;
        int b = bj / JJ, j = bj % JJ;
        const float* p = pos + (size_t)bj * 3;
        float ang = TWOPI_L * (p[2] - 10.0f);
        float s, c; sincosf(ang, &s, &c);
        float2 e1 = make_float2(c, -s);
        float2 e2 = cmul(e1, e1), e4 = cmul(e2, e2), e8 = cmul(e4, e4);
        float2 e15 = cmul(cmul(e8, e4), cmul(e2, e1));
        float2 cur = make_float2(e15.x, -e15.y);
        #pragma unroll
        for (int cc = 0; cc < 31; cc++) {
            g_Ez[b][j][cc] = cur;
            cur = cmul(cur, e1);
        }
    } else if (t < total_xy + BB * JJ + 4 * NBG) {
        int idx = t - total_xy - BB * JJ;
        int k = idx / NBG, n = idx % NBG;
        const float* sp = (k == 0) ? sOO : (k == 1) ? sOH : (k == 2) ? sHO : sHH;
        g_gexp[k][n] = expf(2.0f * sp[n]);
    } else if (t < total_xy + BB * JJ + 4 * NBG + NGRP) {
        g_done[t - total_xy - BB * JJ - 4 * NBG] = 0;
    }
}

// ---------------------------------------------------------------------------
// Kernel 2: nufft1 (scalar, measured-best R12 version).
// 128 threads; warp = 2 rows; lane = cc; 128-particle chunk. grid = 744.
// ---------------------------------------------------------------------------
__global__ __launch_bounds__(128) void nufft1_kernel(const float* __restrict__ charge) {
    int blk = blockIdx.x;
    int rowblk = blk % 62;  blk /= 62;
    int chunk = blk % NCHK; int b = blk / NCHK;
    int w = threadIdx.x >> 5, l = threadIdx.x & 31;
    int rowbase = rowblk * 8;
    int r0 = rowbase + 2 * w, r1 = r0 + 1;
    int jbase = chunk * 128;

    __shared__ float2 shEz[32][32];   // col 31 zeroed (lane-31 mask)
    __shared__ float4 shq[32];
    __shared__ float2 shxy[8][32];    // [block-row][particle]

    float aR0[2] = {0,0}, aI0[2] = {0,0}, aR1[2] = {0,0}, aI1[2] = {0,0};
    float aR2[2] = {0,0}, aI2[2] = {0,0}, aR3[2] = {0,0}, aI3[2] = {0,0};

    for (int j0 = 0; j0 < 128; j0 += 32) {
        __syncthreads();
        for (int idx = threadIdx.x; idx < 32 * 32; idx += 128) {
            int jj = idx >> 5, cc = idx & 31;
            shEz[jj][cc] = (cc < 31) ? g_Ez[b][jbase + j0 + jj][cc]
                                     : make_float2(0.f, 0.f);
        }
        if (threadIdx.x < 32) {
            const float4* q = (const float4*)(charge + (size_t)(b * JJ + jbase + j0 + threadIdx.x) * 4);
            shq[threadIdx.x] = *q;
        }
        {
            int idx = threadIdx.x;
            #pragma unroll
            for (int it = 0; it < 2; it++, idx += 128) {
                int rr = idx >> 5, jj = idx & 31;
                shxy[rr][jj] = g_Exy[b][rowbase + rr][jbase + j0 + jj];
            }
        }
        __syncthreads();
        #pragma unroll 4
        for (int jj = 0; jj < 32; jj++) {
            float2 ez = shEz[jj][l];
            float4 q  = shq[jj];
            float2 t0 = shxy[2 * w][jj];
            float2 t1 = shxy[2 * w + 1][jj];
            float p0r = t0.x*ez.x - t0.y*ez.y;
            float p0i = t0.x*ez.y + t0.y*ez.x;
            float p1r = t1.x*ez.x - t1.y*ez.y;
            float p1i = t1.x*ez.y + t1.y*ez.x;
            aR0[0] += q.x*p0r; aI0[0] += q.x*p0i;
            aR1[0] += q.y*p0r; aI1[0] += q.y*p0i;
            aR2[0] += q.z*p0r; aI2[0] += q.z*p0i;
            aR3[0] += q.w*p0r; aI3[0] += q.w*p0i;
            aR0[1] += q.x*p1r; aI0[1] += q.x*p1i;
            aR1[1] += q.y*p1r; aI1[1] += q.y*p1i;
            aR2[1] += q.z*p1r; aI2[1] += q.z*p1i;
            aR3[1] += q.w*p1r; aI3[1] += q.w*p1i;
        }
    }
    if (l < 31) {
        int i0 = r0 * 31 + l, i1 = r1 * 31 + l;
        g_r[b][chunk][i0][0] = make_float4(aR0[0], aI0[0], aR1[0], aI1[0]);
        g_r[b][chunk][i0][1] = make_float4(aR2[0], aI2[0], aR3[0], aI3[0]);
        g_r[b][chunk][i1][0] = make_float4(aR0[1], aI0[1], aR1[1], aI1[1]);
        g_r[b][chunk][i1][1] = make_float4(aR2[1], aI2[1], aR3[1], aI3[1]);
    }
}

// ---------------------------------------------------------------------------
// Kernel 3: SOG multipliers (gaussian widths from table) + mix + merge + fold.
// ---------------------------------------------------------------------------
__global__ __launch_bounds__(256) void combine_kernel(
    const float* __restrict__ aOO, const float* __restrict__ aOH,
    const float* __restrict__ aHO, const float* __restrict__ aHH)
{
    int idx = blockIdx.x * blockDim.x + threadIdx.x;
    if (idx >= PLANE) return;
    int cc = idx % 31; int t = idx / 31; int bbv = t % 31; int a = t / 31;
    float kx = TWOPI_L * a, ky = TWOPI_L * (bbv - 15), kz = TWOPI_L * (cc - 15);
    float squ = kx*kx + ky*ky + kz*kz;

    bool valid = (a > 0) || (bbv > 15) || (bbv == 15 && cc >= 15);
    bool k0    = (a == 0 && bbv == 15 && cc == 15);

    float mOO = 0.f, mOH = 0.f, mHO = 0.f, mHH = 0.f;
    #pragma unroll
    for (int n = 0; n < NBG; n++) {
        mOO += aOO[n] * expf(-squ * g_gexp[0][n]);
        mOH += aOH[n] * expf(-squ * g_gexp[1][n]);
        mHO += aHO[n] * expf(-squ * g_gexp[2][n]);
        mHH += aHH[n] * expf(-squ * g_gexp[3][n]);
    }
    if (k0) { mOH = 0.f; mHO = 0.f; mHH = 0.f; }
    float wgt = valid ? (k0 ? 1.0f : 2.0f) : 0.0f;
    mOO *= wgt; mOH *= wgt; mHO *= wgt; mHH *= wgt;

    #pragma unroll
    for (int b = 0; b < BB; b++) {
        #pragma unroll
        for (int h = 0; h < 2; h++) {
            float4 c0 = g_r[b][0][idx][h];
            float4 c1 = g_r[b][1][idx][h];
            float4 c2 = g_r[b][2][idx][h];
            float4 c3 = g_r[b][3][idx][h];
            float4 c4 = g_r[b][4][idx][h];
            float4 c5 = g_r[b][5][idx][h];
            float4 rO = make_float4(c0.x + c1.x, c0.y + c1.y, c0.z + c1.z, c0.w + c1.w);
            float4 rH = make_float4(c2.x + c3.x + c4.x + c5.x, c2.y + c3.y + c4.y + c5.y,
                                    c2.z + c3.z + c4.z + c5.z, c2.w + c3.w + c4.w + c5.w);
            g_f[b][0][idx][h] = make_float4(mOO*rO.x + mOH*rH.x, mOO*rO.y + mOH*rH.y,
                                            mOO*rO.z + mOH*rH.z, mOO*rO.w + mOH*rH.w);
            g_f[b][1][idx][h] = make_float4(mHO*rO.x + mHH*rH.x, mHO*rO.y + mHH*rH.y,
                                            mHO*rO.z + mHH*rH.z, mHO*rO.w + mHH*rH.w);
        }
    }
}

// ---------------------------------------------------------------------------
// Kernel 4: nufft2 (R12 measured-best) + FUSED finalize via completion counter.
// 8 warps x 4 particles; one a-value per block. grid = 48*16 = 768.
// ---------------------------------------------------------------------------
__global__ __launch_bounds__(256) void nufft2_kernel(const float* __restrict__ charge,
                                                     float* __restrict__ out) {
    int blk = blockIdx.x;
    int split = blk & 15; int g = blk >> 4;
    int b = g / 24; int gg = g % 24;
    int s = (gg >= 8) ? 1 : 0;
    int pbase = (gg < 8) ? gg * NP2 : 256 + (gg - 8) * NP2;
    int w = threadIdx.x >> 5, l = threadIdx.x & 31;
    int lc = (l < 31) ? l : 30;
    int pb = w * 4;

    __shared__ float4 tileA[961];                  // f channels 0,1 (full a-plane)
    __shared__ float4 tileB[961];                  // f channels 2,3
    __shared__ ull shATx [31][16];                 // packed (Exy.x p0, p1)
    __shared__ ull shATyn[31][16];                 // packed (-Exy.y, -Exy.y)
    __shared__ int sIsLast;

    // ---- stage everything once ----
    {
        const float4* src = &g_f[b][s][split * 961][0];
        for (int t = threadIdx.x; t < 961; t += 256) {
            tileA[t] = src[2 * t];
            tileB[t] = src[2 * t + 1];
        }
        for (int t = threadIdx.x; t < 31 * 16; t += 256) {
            int rr = t >> 4; int pr = t & 15;
            float2 A0 = g_Exy[b][split * 31 + rr][pbase + 2 * pr];
            float2 A1 = g_Exy[b][split * 31 + rr][pbase + 2 * pr + 1];
            ull vx, vy;
            float n0 = -A0.y, n1 = -A1.y;
            PACKF(vx, A0.x, A1.x);
            PACKF(vy, n0, n1);
            shATx[rr][pr] = vx; shATyn[rr][pr] = vy;
        }
    }

    // per-pair packed constants
    ull ezx[2], ezy[2], ezyn[2];
    ull qx[2], qy[2], qz[2], qw[2];
    #pragma unroll
    for (int pr = 0; pr < 2; pr++) {
        int p0 = pbase + pb + 2 * pr, p1 = p0 + 1;
        float2 ea = (l < 31) ? g_Ez[b][p0][lc] : make_float2(0.f, 0.f);
        float2 eb = (l < 31) ? g_Ez[b][p1][lc] : make_float2(0.f, 0.f);
        PACKF(ezx[pr], ea.x, eb.x);
        PACKF(ezy[pr], ea.y, eb.y);
        float na = -ea.y, nb = -eb.y;
        PACKF(ezyn[pr], na, nb);
        float4 qa = *(const float4*)(charge + (size_t)(b * JJ + p0) * 4);
        float4 qb = *(const float4*)(charge + (size_t)(b * JJ + p1) * 4);
        PACKF(qx[pr], qa.x, qb.x); PACKF(qy[pr], qa.y, qb.y);
        PACKF(qz[pr], qa.z, qb.z); PACKF(qw[pr], qa.w, qb.w);
    }
    ull accE1[2] = {0ull, 0ull}, accE2[2] = {0ull, 0ull};
    ull accS[2] = {0ull, 0ull}, accY[2] = {0ull, 0ull};

    __syncthreads();

    for (int row = 0; row < 31; row++) {
        float4 fa = tileA[row * 31 + lc];
        float4 fb = tileB[row * 31 + lc];
        ull f0r, f0i, f1r, f1i, f2r, f2i, f3r, f3i, kys;
        PACKF(f0r, fa.x, fa.x); PACKF(f0i, fa.y, fa.y);
        PACKF(f1r, fa.z, fa.z); PACKF(f1i, fa.w, fa.w);
        PACKF(f2r, fb.x, fb.x); PACKF(f2i, fb.y, fb.y);
        PACKF(f3r, fb.z, fb.z); PACKF(f3i, fb.w, fb.w);
        float ky = TWOPI_L * (row - 15);
        PACKF(kys, ky, ky);
        #pragma unroll
        for (int pr = 0; pr < 2; pr++) {
            ull Ax  = shATx [row][2 * w + pr];
            ull Ayn = shATyn[row][2 * w + pr];
            ull tt, ur, uiN;
            MUL2(tt, Ayn, ezy[pr]); FMA2(ur,  Ax, ezx[pr],  tt);   //  Re u
            MUL2(tt, Ayn, ezx[pr]); FMA2(uiN, Ax, ezyn[pr], tt);   // -Im u
            ull fqr, fqi;
            MUL2(fqr, qw[pr], f3r); FMA2(fqr, qz[pr], f2r, fqr);
            FMA2(fqr, qy[pr], f1r, fqr); FMA2(fqr, qx[pr], f0r, fqr);
            MUL2(fqi, qw[pr], f3i); FMA2(fqi, qz[pr], f2i, fqi);
            FMA2(fqi, qy[pr], f1i, fqi); FMA2(fqi, qx[pr], f0i, fqi);
            FMA2(accE1[pr], fqr, ur,  accE1[pr]);                  // Σ fqr*ur
            FMA2(accE2[pr], fqi, uiN, accE2[pr]);                  // Σ fqi*(-ui)
            ull wi;
            MUL2(wi, fqr, uiN); FMA2(wi, fqi, ur, wi);             // Im(fq conj u)
            ADD2(accS[pr], accS[pr], wi);
            FMA2(accY[pr], kys, wi, accY[pr]);
        }
    }

    float kxv = TWOPI_L * split;
    float kzv = TWOPI_L * (l - 15);
    #pragma unroll
    for (int pr = 0; pr < 2; pr++) {
        float e1L, e1H, e2L, e2H, sL, sH, yL, yH;
        UNPACKF(e1L, e1H, accE1[pr]);
        UNPACKF(e2L, e2H, accE2[pr]);
        UNPACKF(sL, sH, accS[pr]);
        UNPACKF(yL, yH, accY[pr]);
        #pragma unroll
        for (int half = 0; half < 2; half++) {
            float e = (half ? e1H : e1L) - (half ? e2H : e2L);     // Re(fq conj u)
            float S = half ? sH : sL;
            float Y = half ? yH : yL;
            float Z = S * kzv;
            #pragma unroll
            for (int off = 16; off > 0; off >>= 1) {
                e += __shfl_xor_sync(0xffffffff, e, off);
                S += __shfl_xor_sync(0xffffffff, S, off);
                Y += __shfl_xor_sync(0xffffffff, Y, off);
                Z += __shfl_xor_sync(0xffffffff, Z, off);
            }
            if (l == 0) {
                int j = pbase + pb + 2 * pr + half;
                g_part[split][b][j][0] = e;
                g_part[split][b][j][1] = kxv * S;
                g_part[split][b][j][2] = Y;
                g_part[split][b][j][3] = Z;
            }
        }
    }

    // ---- fused finalize: last block of this group reduces all 16 splits ----
    __threadfence();
    __syncthreads();
    if (threadIdx.x == 0) {
        int old = atomicAdd(&g_done[g], 1);
        sIsLast = (old == NSPLIT - 1) ? 1 : 0;
    }
    __syncthreads();
    if (sIsLast) {
        __threadfence();
        for (int t = threadIdx.x; t < NP2 * 4; t += 256) {
            int p = t >> 2, comp = t & 3;
            int j = pbase + p;
            float acc = 0.f;
            #pragma unroll
            for (int sp = 0; sp < NSPLIT; sp++)
                acc += g_part[sp][b][j][comp];
            if (comp == 0) {
                out[b * JJ + j] = acc * (1.0f / (2.0f * VBOX));
            } else {
                float* F = out + BB * JJ;
                F[(size_t)(b * JJ + j) * 3 + (comp - 1)] = acc * (1.0f / VBOX);
            }
        }
    }
}

// ---------------------------------------------------------------------------
extern "C" void kernel_launch(void* const* d_in, const int* in_sizes, int n_in,
                              void* d_out, int out_size) {
    const float* pos    = (const float*)d_in[0];
    const float* charge = (const float*)d_in[1];

    int phase_threads = (NA + 1) * BB * JJ + 4 * NBG + NGRP;
    phase_kernel<<<(phase_threads + 255) / 256, 256>>>(
        pos, (const float*)d_in[2], (const float*)d_in[4],
        (const float*)d_in[6], (const float*)d_in[8]);
    nufft1_kernel<<<BB * NCHK * 62, 128>>>(charge);
    combine_kernel<<<(PLANE + 255) / 256, 256>>>(
        (const float*)d_in[3], (const float*)d_in[5],
        (const float*)d_in[7], (const float*)d_in[9]);
    nufft2_kernel<<<48 * NSPLIT, 256>>>(charge, (float*)d_out);
}